// round 8
// baseline (speedup 1.0000x reference)
#include <cuda_runtime.h>
#include <cstddef>
#include <cstdint>

// Problem constants
#define PB 4
#define PN 16384
#define PM 16384
#define PK 16
#define PC 64
#define PO 64
#define PG 8

typedef unsigned long long ull;

// ---- f32x2 packed helpers (sm_103a FFMA2 path) ----
__device__ __forceinline__ void ffma2(ull& d, ull a, ull b, ull c) {
    asm("fma.rn.f32x2 %0, %1, %2, %3;" : "=l"(d) : "l"(a), "l"(b), "l"(c));
}
__device__ __forceinline__ void fmul2(ull& d, ull a, ull b) {
    asm("mul.rn.f32x2 %0, %1, %2;" : "=l"(d) : "l"(a), "l"(b));
}
__device__ __forceinline__ void fadd2(ull& d, ull a, ull b) {
    asm("add.rn.f32x2 %0, %1, %2;" : "=l"(d) : "l"(a), "l"(b));
}
__device__ __forceinline__ ull pack2(float lo, float hi) {
    ull r; asm("mov.b64 %0, {%1, %2};" : "=l"(r) : "f"(lo), "f"(hi)); return r;
}
__device__ __forceinline__ float2 unpack2(ull v) {
    float2 f; asm("mov.b64 {%0, %1}, %2;" : "=f"(f.x), "=f"(f.y) : "l"(v)); return f;
}
__device__ __forceinline__ ull lds64(uint32_t a) {
    ull r; asm volatile("ld.shared.b64 %0, [%1];" : "=l"(r) : "r"(a)); return r;
}
__device__ __forceinline__ void lds128(ull& x, ull& y, uint32_t a) {
    asm volatile("ld.shared.v2.b64 {%0,%1}, [%2];" : "=l"(x), "=l"(y) : "r"(a));
}
__device__ __forceinline__ void sts128(uint32_t a, ull x, ull y) {
    asm volatile("st.shared.v2.b64 [%0], {%1,%2};" :: "r"(a), "l"(x), "l"(y) : "memory");
}
__device__ __forceinline__ void ldg128(ull& x, ull& y, const void* p) {
    asm volatile("ld.global.nc.v2.b64 {%0,%1}, [%2];" : "=l"(x), "=l"(y) : "l"(p));
}
__device__ __forceinline__ void stg128(void* p, ull x, ull y) {
    asm volatile("st.global.v2.b64 [%0], {%1,%2};" :: "l"(p), "l"(x), "l"(y) : "memory");
}

static __device__ float g_xv[PB * PN * PO];   // x_v [B,N,64]
static __device__ float g_a [PB * PN * PG];   // per-point logit precursor [B,N,8]
static __device__ float g_c [PB * PM * PG];   // per-center logit precursor [B,M,8]
static __device__ float g_wka[PC * PG];
static __device__ float g_wqa[PC * PG];
static __device__ float g_wca[PO * PG];
static __device__ float g_c0[PG];
static __device__ float g_a0[PG];
static __device__ float g_pw1f[3 * PO];       // pe_w1 col-scaled by pe_s
static __device__ float g_cw1f[3 * PO];       // cpe_w1 col-scaled by cpe_s
static __device__ float g_we2i[64];           // we_w2 interleaved pairs {w[gp][q], w[gp][q+4]}
static __device__ float g_web2i[8];           // we_b2 interleaved {b[q], b[q+4]}
static __device__ float g_pw2p[4096];         // pe_w2 paired: slot(j,q,rp) -> {w[j][8q+2rp], w[j][8q+2rp+32], w[j][8q+2rp+1], w[j][8q+2rp+33]}

// ---------------------------------------------------------------------------
// Kernel 0: fold small weight combos
// ---------------------------------------------------------------------------
__global__ void fold_kernel(const float* __restrict__ Wq, const float* __restrict__ bq,
                            const float* __restrict__ Wk, const float* __restrict__ bk,
                            const float* __restrict__ cpe_w1, const float* __restrict__ cpe_s,
                            const float* __restrict__ cpe_w2, const float* __restrict__ cpe_b2,
                            const float* __restrict__ pe_w1, const float* __restrict__ pe_s,
                            const float* __restrict__ pe_w2,
                            const float* __restrict__ we_w1, const float* __restrict__ we_s,
                            const float* __restrict__ we_b,
                            const float* __restrict__ we_w2, const float* __restrict__ we_b2) {
    int tid = threadIdx.x;             // 512 threads
    int c = tid >> 3, g = tid & 7;
    float s = we_s[g];
    float aK = 0.f, aQ = 0.f, aC = 0.f;
    #pragma unroll 8
    for (int o = 0; o < 64; o++) {
        float w1 = we_w1[o * 8 + g];
        aK = fmaf(Wk[c * 64 + o],     w1, aK);
        aQ = fmaf(Wq[c * 64 + o],     w1, aQ);
        aC = fmaf(cpe_w2[c * 64 + o], w1, aC);
    }
    g_wka[c * 8 + g] = aK * s;
    g_wqa[c * 8 + g] = aQ * s;
    g_wca[c * 8 + g] = aC * s;

    if (tid < 8) {
        float a0 = 0.f, c0 = 0.f;
        for (int o = 0; o < 64; o++) {
            float w1 = we_w1[o * 8 + tid];
            a0 = fmaf(bk[o], w1, a0);
            c0 = fmaf(bq[o] - cpe_b2[o], w1, c0);
        }
        g_a0[tid] = a0 * we_s[tid];
        g_c0[tid] = c0 * we_s[tid] - we_b[tid];
    }
    if (tid < 192) {
        int j = tid % 64;
        g_pw1f[tid] = pe_w1[tid]  * pe_s[j];
        g_cw1f[tid] = cpe_w1[tid] * cpe_s[j];
    }
    // interleaved we_w2 pairs: I[gp][2q+h] = we_w2[gp*8 + q + 4h]
    if (tid < 64) {
        int gp = tid >> 3, q = (tid & 7) >> 1, h = tid & 1;
        g_we2i[tid] = we_w2[gp * 8 + q + 4 * h];
    }
    if (tid < 8) {
        int q = tid >> 1, h = tid & 1;
        g_web2i[tid] = we_b2[q + 4 * h];
    }
    // paired pe_w2: 1024 slots of 4 floats; slot s: j=s>>4, q=(s>>2)&3, rp=s&3
    #pragma unroll
    for (int w = 0; w < 2; w++) {
        int sl = tid * 2 + w;
        int j = sl >> 4, q = (sl >> 2) & 3, rp = sl & 3;
        int o0 = 8 * q + 2 * rp;
        float4 v;
        v.x = pe_w2[j * 64 + o0];
        v.y = pe_w2[j * 64 + o0 + 32];
        v.z = pe_w2[j * 64 + o0 + 1];
        v.w = pe_w2[j * 64 + o0 + 33];
        *(float4*)(g_pw2p + sl * 4) = v;
    }
}

// ---------------------------------------------------------------------------
// Kernel 1: per-point precompute with packed f32x2 accumulators.
// ---------------------------------------------------------------------------
__global__ void __launch_bounds__(256, 2)
point_kernel(const float* __restrict__ fea,
             const float* __restrict__ Wv,
             const float* __restrict__ bv) {
    __shared__ float sWv[64 * 64];
    __shared__ float sWka[64 * 8];
    __shared__ float sbv[64];
    __shared__ float sa0[8];
    int tid = threadIdx.x;
    for (int i = tid; i < 4096; i += 256) sWv[i] = Wv[i];
    for (int i = tid; i < 512; i += 256)  sWka[i] = g_wka[i];
    if (tid < 64) sbv[tid] = bv[tid];
    if (tid < 8)  sa0[tid] = g_a0[tid];
    __syncthreads();

    uint32_t aWv = (uint32_t)__cvta_generic_to_shared(sWv);
    uint32_t aKa = (uint32_t)__cvta_generic_to_shared(sWka);
    uint32_t aBv = (uint32_t)__cvta_generic_to_shared(sbv);
    uint32_t aA0 = (uint32_t)__cvta_generic_to_shared(sa0);

    int gp = blockIdx.x * 256 + tid;
    int b = gp >> 14;
    int n = gp & (PN - 1);
    const float* fp = fea + (size_t)b * PC * PN + n;

    ull acc2[32];
    ull ag2[4];
    #pragma unroll
    for (int i = 0; i < 32; i++) acc2[i] = lds64(aBv + i * 8);
    #pragma unroll
    for (int i = 0; i < 4; i++)  ag2[i]  = lds64(aA0 + i * 8);

    #pragma unroll 4
    for (int c = 0; c < 64; c++) {
        float f = fp[(size_t)c * PN];
        ull ff = pack2(f, f);
        uint32_t rowa = aWv + c * 256;
        #pragma unroll
        for (int p = 0; p < 16; p++) {
            ull w0, w1;
            lds128(w0, w1, rowa + p * 16);
            ffma2(acc2[p * 2 + 0], ff, w0, acc2[p * 2 + 0]);
            ffma2(acc2[p * 2 + 1], ff, w1, acc2[p * 2 + 1]);
        }
        ull k0, k1, k2, k3;
        lds128(k0, k1, aKa + c * 32);
        lds128(k2, k3, aKa + c * 32 + 16);
        ffma2(ag2[0], ff, k0, ag2[0]);
        ffma2(ag2[1], ff, k1, ag2[1]);
        ffma2(ag2[2], ff, k2, ag2[2]);
        ffma2(ag2[3], ff, k3, ag2[3]);
    }

    float* ov = g_xv + (size_t)gp * 64;
    #pragma unroll
    for (int p = 0; p < 16; p++)
        stg128(ov + p * 4, acc2[p * 2], acc2[p * 2 + 1]);
    float* av = g_a + (size_t)gp * 8;
    stg128(av,     ag2[0], ag2[1]);
    stg128(av + 4, ag2[2], ag2[3]);
}

// ---------------------------------------------------------------------------
// Kernel 2: per-center precompute
// ---------------------------------------------------------------------------
__global__ void center_kernel(const float* __restrict__ center_pos,
                              const float* __restrict__ center_fea,
                              const float* __restrict__ cpe_b) {
    __shared__ float sWqa[512];
    __shared__ float sWca[512];
    __shared__ float sw1[192];
    __shared__ float sb1[64];
    int tid = threadIdx.x;
    for (int i = tid; i < 512; i += 256) { sWqa[i] = g_wqa[i]; sWca[i] = g_wca[i]; }
    if (tid < 192) sw1[tid] = g_cw1f[tid];
    if (tid < 64)  sb1[tid] = cpe_b[tid];
    __syncthreads();

    int gid = blockIdx.x * 256 + tid;
    float px = center_pos[(size_t)gid * 3 + 0];
    float py = center_pos[(size_t)gid * 3 + 1];
    float pz = center_pos[(size_t)gid * 3 + 2];

    float acc[8];
    #pragma unroll
    for (int g = 0; g < 8; g++) acc[g] = __ldg(g_c0 + g);

    int b = gid >> 14;
    int m = gid & (PM - 1);
    const float* cf = center_fea + (size_t)b * PC * PM + m;
    #pragma unroll 4
    for (int i = 0; i < 64; i++) {
        float h = fmaxf(fmaf(px, sw1[i], fmaf(py, sw1[64 + i], fmaf(pz, sw1[128 + i], sb1[i]))), 0.f);
        float f = cf[(size_t)i * PM];
        const float4* qa = (const float4*)(sWqa + i * 8);
        const float4* ca = (const float4*)(sWca + i * 8);
        float4 q0 = qa[0], q1 = qa[1], c0 = ca[0], c1 = ca[1];
        acc[0] += f * q0.x - h * c0.x;  acc[1] += f * q0.y - h * c0.y;
        acc[2] += f * q0.z - h * c0.z;  acc[3] += f * q0.w - h * c0.w;
        acc[4] += f * q1.x - h * c1.x;  acc[5] += f * q1.y - h * c1.y;
        acc[6] += f * q1.z - h * c1.z;  acc[7] += f * q1.w - h * c1.w;
    }
    float4* cv = (float4*)(g_c + (size_t)gid * 8);
    cv[0] = make_float4(acc[0], acc[1], acc[2], acc[3]);
    cv[1] = make_float4(acc[4], acc[5], acc[6], acc[7]);
}

// ---------------------------------------------------------------------------
// Kernel 3: main attention. 128 thr/block = 8 centers x 16 threads.
// Epilogue pe_w2 pairs staged in SMEM (restored from R3 — LDG version stalled
// the LSU). Edge-loop wt extracted from already-loaded pairs via register
// selects (no lds32).
// ---------------------------------------------------------------------------
// smem float layout:
//   0     s_we2i  [64]
//   64    s_web2i [8]
//   72    s_ikd   [8*16 float4] = 512   ({dx,dy,dz,ik_bits})
//   584   s_we    [8*16*8] = 1024       (interleaved raw-e pairs; s_out overlay)
//   1608  s_H     [8 ci * 4 q * 132] = 4224  (pair rows {H[q][j],H[q+4][j]}, pad 4)
//   5832  s_pw    [4096]                (paired pe_w2 table)
#define SM_WE2I  0
#define SM_WEB2I 64
#define SM_IKD   72
#define SM_WE    584
#define SM_HB    1608
#define SM_PW    5832
#define SM_TOT   (5832 + 4096)

__global__ void __launch_bounds__(128, 5)
attn_kernel(const float* __restrict__ center_pos,
            const float* __restrict__ pos,
            const int* __restrict__ idx,
            const float* __restrict__ pe_b,
            const float* __restrict__ pe_b2,
            float* __restrict__ out) {
    extern __shared__ float sm[];
    float*  s_we2i = sm + SM_WE2I;
    float4* s_ikd  = (float4*)(sm + SM_IKD);

    const int tid = threadIdx.x;
    if (tid < 64) s_we2i[tid] = g_we2i[tid];
    if (tid >= 64 && tid < 72) sm[SM_WEB2I + tid - 64] = g_web2i[tid - 64];
    // stage paired pe_w2 table (4096 floats, coalesced float4)
    {
        float4* dst = (float4*)(sm + SM_PW);
        const float4* src = (const float4*)g_pw2p;
        #pragma unroll
        for (int i = 0; i < 8; i++)
            dst[i * 128 + tid] = src[i * 128 + tid];
    }
    __syncthreads();

    const unsigned FULL = 0xffffffffu;
    const int ci = tid >> 4;           // center within block (0..7)
    const int t  = tid & 15;           // lane within center
    const int g  = t >> 1;             // group for onv
    const int gidBase = blockIdx.x * 8;
    const int gid = gidBase + ci;
    const int b = gid >> 14;

    const uint32_t aBase = (uint32_t)__cvta_generic_to_shared(sm);
    const uint32_t aWE   = aBase + SM_WE * 4 + ci * 512;     // this center's e-pairs

    // --- prologue: my edge (k = t) ---
    int myik;
    {
        int ik = idx[(size_t)gid * 16 + t];
        myik = b * PN + ik;
        const float* pp = pos + (size_t)myik * 3;
        float cx = center_pos[(size_t)gid * 3 + 0];
        float cy = center_pos[(size_t)gid * 3 + 1];
        float cz = center_pos[(size_t)gid * 3 + 2];
        s_ikd[ci * 16 + t] = make_float4(pp[0] - cx, pp[1] - cy, pp[2] - cz,
                                         __int_as_float(myik));
    }

    // --- logits (packed pairs over {q, q+4}) + raw exp + sum ---
    ull invP[4];
    {
        const float4* cpv = (const float4*)(g_c + (size_t)gid * 8);
        float4 cA = cpv[0], cB = cpv[1];
        const float4* ap = (const float4*)(g_a + (size_t)myik * 8);
        float4 a0 = ap[0], a1 = ap[1];
        float h1[8];
        h1[0] = fmaxf(a0.x - cA.x, 0.f); h1[1] = fmaxf(a0.y - cA.y, 0.f);
        h1[2] = fmaxf(a0.z - cA.z, 0.f); h1[3] = fmaxf(a0.w - cA.w, 0.f);
        h1[4] = fmaxf(a1.x - cB.x, 0.f); h1[5] = fmaxf(a1.y - cB.y, 0.f);
        h1[6] = fmaxf(a1.z - cB.z, 0.f); h1[7] = fmaxf(a1.w - cB.w, 0.f);

        ull lgP[4];
        lds128(lgP[0], lgP[1], aBase + SM_WEB2I * 4);
        lds128(lgP[2], lgP[3], aBase + SM_WEB2I * 4 + 16);
        #pragma unroll
        for (int gp = 0; gp < 8; gp++) {
            ull w01, w23, w45, w67;
            lds128(w01, w23, aBase + SM_WE2I * 4 + gp * 32);
            lds128(w45, w67, aBase + SM_WE2I * 4 + gp * 32 + 16);
            ull hd = pack2(h1[gp], h1[gp]);
            ffma2(lgP[0], hd, w01, lgP[0]);
            ffma2(lgP[1], hd, w23, lgP[1]);
            ffma2(lgP[2], hd, w45, lgP[2]);
            ffma2(lgP[3], hd, w67, lgP[3]);
        }
        // raw exp (no max-sub: logits are O(0.1))
        ull eP[4], sumP[4];
        #pragma unroll
        for (int q = 0; q < 4; q++) {
            float2 lv = unpack2(lgP[q]);
            eP[q] = pack2(__expf(lv.x), __expf(lv.y));
            sumP[q] = eP[q];
        }
        // store raw-e pairs for this edge
        sts128(aWE + t * 32,      eP[0], eP[1]);
        sts128(aWE + t * 32 + 16, eP[2], eP[3]);
        // packed sum butterfly over 16 lanes
        #pragma unroll
        for (int s = 1; s < 16; s <<= 1) {
            #pragma unroll
            for (int q = 0; q < 4; q++) {
                ull o = __shfl_xor_sync(FULL, sumP[q], s, 16);
                fadd2(sumP[q], sumP[q], o);
            }
        }
        #pragma unroll
        for (int q = 0; q < 4; q++) {
            float2 sv = unpack2(sumP[q]);
            invP[q] = pack2(__fdividef(1.f, sv.x), __fdividef(1.f, sv.y));
        }
    }
    __syncwarp();

    // --- per-thread pe_w1 slice (folded with pe_s) + bias ---
    float wxa[4], wxb[4], wxc[4], bb[4];
    #pragma unroll
    for (int jj = 0; jj < 4; jj++) {
        wxa[jj] = __ldg(g_pw1f + 0 * 64 + t * 4 + jj);
        wxb[jj] = __ldg(g_pw1f + 1 * 64 + t * 4 + jj);
        wxc[jj] = __ldg(g_pw1f + 2 * 64 + t * 4 + jj);
        bb[jj]  = __ldg(pe_b + t * 4 + jj);
    }

    // --- edge loop ---
    // Hc2[jl*4+q] = {H[q][4t+jl], H[q+4][4t+jl]}  (unnormalized)
    ull Hc2[16];
    ull onv2[2] = {0ull, 0ull};
    #pragma unroll
    for (int i = 0; i < 16; i++) Hc2[i] = 0ull;

    const bool gsel1 = (g & 1), gsel2 = (g & 2), gsel4 = (g & 4);
    #pragma unroll
    for (int k = 0; k < 16; k++) {
        float4 d = *(float4*)((char*)sm + (SM_IKD * 4 + ci * 256 + k * 16));
        int ikk = __float_as_int(d.w);
        ull wp0, wp1, wp2, wp3;
        lds128(wp0, wp1, aWE + k * 32);
        lds128(wp2, wp3, aWE + k * 32 + 16);
        ull v0, v1;
        ldg128(v0, v1, g_xv + (size_t)ikk * 64 + t * 4);

        float h0 = fmaxf(fmaf(d.x, wxa[0], fmaf(d.y, wxb[0], fmaf(d.z, wxc[0], bb[0]))), 0.f);
        float h1 = fmaxf(fmaf(d.x, wxa[1], fmaf(d.y, wxb[1], fmaf(d.z, wxc[1], bb[1]))), 0.f);
        float h2 = fmaxf(fmaf(d.x, wxa[2], fmaf(d.y, wxb[2], fmaf(d.z, wxc[2], bb[2]))), 0.f);
        float h3 = fmaxf(fmaf(d.x, wxa[3], fmaf(d.y, wxb[3], fmaf(d.z, wxc[3], bb[3]))), 0.f);
        ull hd0 = pack2(h0, h0), hd1 = pack2(h1, h1);
        ull hd2 = pack2(h2, h2), hd3 = pack2(h3, h3);

        ffma2(Hc2[0],  wp0, hd0, Hc2[0]);  ffma2(Hc2[1],  wp1, hd0, Hc2[1]);
        ffma2(Hc2[2],  wp2, hd0, Hc2[2]);  ffma2(Hc2[3],  wp3, hd0, Hc2[3]);
        ffma2(Hc2[4],  wp0, hd1, Hc2[4]);  ffma2(Hc2[5],  wp1, hd1, Hc2[5]);
        ffma2(Hc2[6],  wp2, hd1, Hc2[6]);  ffma2(Hc2[7],  wp3, hd1, Hc2[7]);
        ffma2(Hc2[8],  wp0, hd2, Hc2[8]);  ffma2(Hc2[9],  wp1, hd2, Hc2[9]);
        ffma2(Hc2[10], wp2, hd2, Hc2[10]); ffma2(Hc2[11], wp3, hd2, Hc2[11]);
        ffma2(Hc2[12], wp0, hd3, Hc2[12]); ffma2(Hc2[13], wp1, hd3, Hc2[13]);
        ffma2(Hc2[14], wp2, hd3, Hc2[14]); ffma2(Hc2[15], wp3, hd3, Hc2[15]);

        // wt = e_g extracted from the pairs already in registers
        ull sa = gsel1 ? wp1 : wp0;
        ull sb = gsel1 ? wp3 : wp2;
        ull sc = gsel2 ? sb : sa;
        float2 sf = unpack2(sc);
        float wt = gsel4 ? sf.y : sf.x;
        ull wtp = pack2(wt, wt);
        ffma2(onv2[0], wtp, v0, onv2[0]);
        ffma2(onv2[1], wtp, v1, onv2[1]);
    }

    // --- normalize: Hc2 *= invP[q];  onv2 *= inv_g ---
    #pragma unroll
    for (int jl = 0; jl < 4; jl++)
        #pragma unroll
        for (int q = 0; q < 4; q++)
            fmul2(Hc2[jl * 4 + q], Hc2[jl * 4 + q], invP[q]);
    {
        ull ip = (g & 3) == 0 ? invP[0] : (g & 3) == 1 ? invP[1] : (g & 3) == 2 ? invP[2] : invP[3];
        float2 iv = unpack2(ip);
        float invg = gsel4 ? iv.y : iv.x;
        ull ig = pack2(invg, invg);
        fmul2(onv2[0], onv2[0], ig);
        fmul2(onv2[1], onv2[1], ig);
    }

    // --- store H pair-rows to smem (warp-local) ---
    {
        uint32_t aH = aBase + SM_HB * 4 + ci * 4 * 528 + t * 32;
        #pragma unroll
        for (int q = 0; q < 4; q++) {
            sts128(aH + q * 528,      Hc2[0 * 4 + q], Hc2[1 * 4 + q]);
            sts128(aH + q * 528 + 16, Hc2[2 * 4 + q], Hc2[3 * 4 + q]);
        }
    }
    __syncthreads();   // all warps past s_we reads -> safe to overlay s_out

    // --- phase 1: onv to staging (o = 4t..4t+3) ---
    float* s_out = sm + SM_WE;   // 64 x 9 overlay
    {
        float2 a0 = unpack2(onv2[0]), a1 = unpack2(onv2[1]);
        s_out[(t * 4 + 0) * 9 + ci] = a0.x;
        s_out[(t * 4 + 1) * 9 + ci] = a0.y;
        s_out[(t * 4 + 2) * 9 + ci] = a1.x;
        s_out[(t * 4 + 3) * 9 + ci] = a1.y;
    }

    // --- pr contraction: thread (q=t&3, rp=t>>2) -> outputs {oa0,oa1} and +32 ---
    const int q  = t & 3;
    const int rp = t >> 2;
    const int oa0 = 8 * q + 2 * rp;
    ull prP0 = pack2(__ldg(pe_b2 + oa0),     __ldg(pe_b2 + oa0 + 32));
    ull prP1 = pack2(__ldg(pe_b2 + oa0 + 1), __ldg(pe_b2 + oa0 + 33));
    {
        uint32_t aHr = aBase + SM_HB * 4 + (ci * 4 + q) * 528;
        uint32_t aPW = aBase + SM_PW * 4 + (q * 4 + rp) * 16;
        #pragma unroll 8
        for (int j = 0; j < 64; j += 2) {
            ull Hj0, Hj1;
            lds128(Hj0, Hj1, aHr + j * 8);
            ull p0, p1;
            lds128(p0, p1, aPW + j * 256);
            ffma2(prP0, Hj0, p0, prP0);
            ffma2(prP1, Hj0, p1, prP1);
            lds128(p0, p1, aPW + (j + 1) * 256);
            ffma2(prP0, Hj1, p0, prP0);
            ffma2(prP1, Hj1, p1, prP1);
        }
    }
    __syncthreads();   // onv staging complete everywhere

    // --- phase 2: add pr at its o-mapping ---
    {
        float2 P0 = unpack2(prP0), P1 = unpack2(prP1);
        s_out[(oa0)      * 9 + ci] += P0.x;
        s_out[(oa0 + 1)  * 9 + ci] += P1.x;
        s_out[(oa0 + 32) * 9 + ci] += P0.y;
        s_out[(oa0 + 33) * 9 + ci] += P1.y;
    }
    __syncthreads();

    const int m0 = gidBase & (PM - 1);
    float* ob = out + (size_t)(gidBase >> 14) * PO * PM + m0;
    #pragma unroll
    for (int qq = 0; qq < 4; qq++) {
        int lin = qq * 128 + tid;
        int o = lin >> 3;
        int ml = lin & 7;
        ob[(size_t)o * PM + ml] = s_out[o * 9 + ml];
    }
}

// ---------------------------------------------------------------------------
extern "C" void kernel_launch(void* const* d_in, const int* in_sizes, int n_in,
                              void* d_out, int out_size) {
    (void)in_sizes; (void)n_in; (void)out_size;
    const float* center_pos = (const float*)d_in[0];
    const float* center_fea = (const float*)d_in[1];
    const float* pos        = (const float*)d_in[2];
    const float* fea        = (const float*)d_in[3];
    const int*   idx        = (const int*)d_in[4];
    const float* Wq  = (const float*)d_in[5];
    const float* bq  = (const float*)d_in[6];
    const float* Wk  = (const float*)d_in[7];
    const float* bk  = (const float*)d_in[8];
    const float* Wv  = (const float*)d_in[9];
    const float* bv  = (const float*)d_in[10];
    const float* cpe_w1 = (const float*)d_in[11];
    const float* cpe_s  = (const float*)d_in[12];
    const float* cpe_b  = (const float*)d_in[13];
    const float* cpe_w2 = (const float*)d_in[14];
    const float* cpe_b2 = (const float*)d_in[15];
    const float* pe_w1  = (const float*)d_in[16];
    const float* pe_s   = (const float*)d_in[17];
    const float* pe_b   = (const float*)d_in[18];
    const float* pe_w2  = (const float*)d_in[19];
    const float* pe_b2  = (const float*)d_in[20];
    const float* we_w1  = (const float*)d_in[21];
    const float* we_s   = (const float*)d_in[22];
    const float* we_b   = (const float*)d_in[23];
    const float* we_w2  = (const float*)d_in[24];
    const float* we_b2  = (const float*)d_in[25];
    float* out = (float*)d_out;

    fold_kernel<<<1, 512>>>(Wq, bq, Wk, bk, cpe_w1, cpe_s, cpe_w2, cpe_b2,
                            pe_w1, pe_s, pe_w2, we_w1, we_s, we_b, we_w2, we_b2);
    point_kernel<<<(PB * PN) / 256, 256>>>(fea, Wv, bv);
    center_kernel<<<(PB * PM) / 256, 256>>>(center_pos, center_fea, cpe_b);

    const int smem = SM_TOT * 4;   // ~39.7 KB
    cudaFuncSetAttribute(attn_kernel, cudaFuncAttributeMaxDynamicSharedMemorySize, smem);
    attn_kernel<<<(PB * PM) / 8, 128, smem>>>(center_pos, pos, idx,
                                              pe_b, pe_b2, out);
}

// round 9
// speedup vs baseline: 1.2574x; 1.2574x over previous
#include <cuda_runtime.h>
#include <cstddef>
#include <cstdint>

// Problem constants
#define PB 4
#define PN 16384
#define PM 16384
#define PK 16
#define PC 64
#define PO 64
#define PG 8

typedef unsigned long long ull;

// ---- f32x2 packed helpers (sm_103a FFMA2 path) ----
__device__ __forceinline__ void ffma2(ull& d, ull a, ull b, ull c) {
    asm("fma.rn.f32x2 %0, %1, %2, %3;" : "=l"(d) : "l"(a), "l"(b), "l"(c));
}
__device__ __forceinline__ ull pack2(float lo, float hi) {
    ull r; asm("mov.b64 %0, {%1, %2};" : "=l"(r) : "f"(lo), "f"(hi)); return r;
}
__device__ __forceinline__ float2 unpack2(ull v) {
    float2 f; asm("mov.b64 {%0, %1}, %2;" : "=f"(f.x), "=f"(f.y) : "l"(v)); return f;
}
__device__ __forceinline__ ull lds64(uint32_t a) {
    ull r; asm volatile("ld.shared.b64 %0, [%1];" : "=l"(r) : "r"(a)); return r;
}
__device__ __forceinline__ void lds128(ull& x, ull& y, uint32_t a) {
    asm volatile("ld.shared.v2.b64 {%0,%1}, [%2];" : "=l"(x), "=l"(y) : "r"(a));
}
__device__ __forceinline__ void sts128(uint32_t a, ull x, ull y) {
    asm volatile("st.shared.v2.b64 [%0], {%1,%2};" :: "r"(a), "l"(x), "l"(y) : "memory");
}
__device__ __forceinline__ void ldg128(ull& x, ull& y, const void* p) {
    asm volatile("ld.global.nc.v2.b64 {%0,%1}, [%2];" : "=l"(x), "=l"(y) : "l"(p));
}
__device__ __forceinline__ void stg128(void* p, ull x, ull y) {
    asm volatile("st.global.v2.b64 [%0], {%1,%2};" :: "l"(p), "l"(x), "l"(y) : "memory");
}

static __device__ float g_xv[PB * PN * PO];   // x_v [B,N,64]
static __device__ float g_a [PB * PN * PG];   // per-point logit precursor [B,N,8]
static __device__ float g_c [PB * PM * PG];   // per-center logit precursor [B,M,8]
static __device__ float g_wka[PC * PG];
static __device__ float g_wqa[PC * PG];
static __device__ float g_wca[PO * PG];
static __device__ float g_c0[PG];
static __device__ float g_a0[PG];
static __device__ float g_pw1f[3 * PO];       // pe_w1 col-scaled by pe_s
static __device__ float g_cw1f[3 * PO];       // cpe_w1 col-scaled by cpe_s

// ---------------------------------------------------------------------------
// Kernel 0: fold small weight combos (R3 version)
// ---------------------------------------------------------------------------
__global__ void fold_kernel(const float* __restrict__ Wq, const float* __restrict__ bq,
                            const float* __restrict__ Wk, const float* __restrict__ bk,
                            const float* __restrict__ cpe_w1, const float* __restrict__ cpe_s,
                            const float* __restrict__ cpe_w2, const float* __restrict__ cpe_b2,
                            const float* __restrict__ pe_w1, const float* __restrict__ pe_s,
                            const float* __restrict__ we_w1, const float* __restrict__ we_s,
                            const float* __restrict__ we_b) {
    int tid = threadIdx.x;             // 512 threads
    int c = tid >> 3, g = tid & 7;
    float s = we_s[g];
    float aK = 0.f, aQ = 0.f, aC = 0.f;
    #pragma unroll 8
    for (int o = 0; o < 64; o++) {
        float w1 = we_w1[o * 8 + g];
        aK = fmaf(Wk[c * 64 + o],     w1, aK);
        aQ = fmaf(Wq[c * 64 + o],     w1, aQ);
        aC = fmaf(cpe_w2[c * 64 + o], w1, aC);
    }
    g_wka[c * 8 + g] = aK * s;
    g_wqa[c * 8 + g] = aQ * s;
    g_wca[c * 8 + g] = aC * s;

    if (tid < 8) {
        float a0 = 0.f, c0 = 0.f;
        for (int o = 0; o < 64; o++) {
            float w1 = we_w1[o * 8 + tid];
            a0 = fmaf(bk[o], w1, a0);
            c0 = fmaf(bq[o] - cpe_b2[o], w1, c0);
        }
        g_a0[tid] = a0 * we_s[tid];
        g_c0[tid] = c0 * we_s[tid] - we_b[tid];
    }
    if (tid < 192) {
        int j = tid % 64;
        g_pw1f[tid] = pe_w1[tid]  * pe_s[j];
        g_cw1f[tid] = cpe_w1[tid] * cpe_s[j];
    }
}

// ---------------------------------------------------------------------------
// Kernel 1: per-point precompute. 128 thr/block, TWO adjacent points/thread:
// fea is [C][N] so {f[c][n], f[c][n+1]} is one ld.global.f64; the 18 weight
// LDS per c-iteration are shared between both points.
// ---------------------------------------------------------------------------
__global__ void __launch_bounds__(128, 2)
point_kernel(const float* __restrict__ fea,
             const float* __restrict__ Wv,
             const float* __restrict__ bv) {
    __shared__ float sWv[64 * 64];
    __shared__ float sWka[64 * 8];
    __shared__ float sbv[64];
    __shared__ float sa0[8];
    int tid = threadIdx.x;
    for (int i = tid; i < 4096; i += 128) sWv[i] = Wv[i];
    for (int i = tid; i < 512; i += 128)  sWka[i] = g_wka[i];
    if (tid < 64) sbv[tid] = bv[tid];
    if (tid < 8)  sa0[tid] = g_a0[tid];
    __syncthreads();

    uint32_t aWv = (uint32_t)__cvta_generic_to_shared(sWv);
    uint32_t aKa = (uint32_t)__cvta_generic_to_shared(sWka);
    uint32_t aBv = (uint32_t)__cvta_generic_to_shared(sbv);
    uint32_t aA0 = (uint32_t)__cvta_generic_to_shared(sa0);

    int gp0 = (blockIdx.x * 128 + tid) * 2;   // two adjacent points (same batch: n even)
    int b = gp0 >> 14;
    int n = gp0 & (PN - 1);
    const float* fp = fea + (size_t)b * PC * PN + n;

    ull accA[32], accB[32];
    ull agA[4],  agB[4];
    #pragma unroll
    for (int i = 0; i < 32; i++) { accA[i] = lds64(aBv + i * 8); accB[i] = accA[i]; }
    #pragma unroll
    for (int i = 0; i < 4; i++)  { agA[i]  = lds64(aA0 + i * 8); agB[i] = agA[i]; }

    #pragma unroll 2
    for (int c = 0; c < 64; c++) {
        float2 f2 = *(const float2*)(fp + (size_t)c * PN);
        ull fA = pack2(f2.x, f2.x);
        ull fB = pack2(f2.y, f2.y);
        uint32_t rowa = aWv + c * 256;
        #pragma unroll
        for (int p = 0; p < 16; p++) {
            ull w0, w1;
            lds128(w0, w1, rowa + p * 16);
            ffma2(accA[p * 2 + 0], fA, w0, accA[p * 2 + 0]);
            ffma2(accA[p * 2 + 1], fA, w1, accA[p * 2 + 1]);
            ffma2(accB[p * 2 + 0], fB, w0, accB[p * 2 + 0]);
            ffma2(accB[p * 2 + 1], fB, w1, accB[p * 2 + 1]);
        }
        ull k0, k1, k2, k3;
        lds128(k0, k1, aKa + c * 32);
        lds128(k2, k3, aKa + c * 32 + 16);
        ffma2(agA[0], fA, k0, agA[0]);  ffma2(agA[1], fA, k1, agA[1]);
        ffma2(agA[2], fA, k2, agA[2]);  ffma2(agA[3], fA, k3, agA[3]);
        ffma2(agB[0], fB, k0, agB[0]);  ffma2(agB[1], fB, k1, agB[1]);
        ffma2(agB[2], fB, k2, agB[2]);  ffma2(agB[3], fB, k3, agB[3]);
    }

    float* ovA = g_xv + (size_t)gp0 * 64;
    float* ovB = ovA + 64;
    #pragma unroll
    for (int p = 0; p < 16; p++) {
        stg128(ovA + p * 4, accA[p * 2], accA[p * 2 + 1]);
        stg128(ovB + p * 4, accB[p * 2], accB[p * 2 + 1]);
    }
    float* avA = g_a + (size_t)gp0 * 8;
    stg128(avA,      agA[0], agA[1]);
    stg128(avA + 4,  agA[2], agA[3]);
    stg128(avA + 8,  agB[0], agB[1]);
    stg128(avA + 12, agB[2], agB[3]);
}

// ---------------------------------------------------------------------------
// Kernel 2: per-center precompute (R3 version, unchanged)
// ---------------------------------------------------------------------------
__global__ void center_kernel(const float* __restrict__ center_pos,
                              const float* __restrict__ center_fea,
                              const float* __restrict__ cpe_b) {
    __shared__ float sWqa[512];
    __shared__ float sWca[512];
    __shared__ float sw1[192];
    __shared__ float sb1[64];
    int tid = threadIdx.x;
    for (int i = tid; i < 512; i += 256) { sWqa[i] = g_wqa[i]; sWca[i] = g_wca[i]; }
    if (tid < 192) sw1[tid] = g_cw1f[tid];
    if (tid < 64)  sb1[tid] = cpe_b[tid];
    __syncthreads();

    int gid = blockIdx.x * 256 + tid;
    float px = center_pos[(size_t)gid * 3 + 0];
    float py = center_pos[(size_t)gid * 3 + 1];
    float pz = center_pos[(size_t)gid * 3 + 2];

    float acc[8];
    #pragma unroll
    for (int g = 0; g < 8; g++) acc[g] = __ldg(g_c0 + g);

    int b = gid >> 14;
    int m = gid & (PM - 1);
    const float* cf = center_fea + (size_t)b * PC * PM + m;
    #pragma unroll 4
    for (int i = 0; i < 64; i++) {
        float h = fmaxf(fmaf(px, sw1[i], fmaf(py, sw1[64 + i], fmaf(pz, sw1[128 + i], sb1[i]))), 0.f);
        float f = cf[(size_t)i * PM];
        const float4* qa = (const float4*)(sWqa + i * 8);
        const float4* ca = (const float4*)(sWca + i * 8);
        float4 q0 = qa[0], q1 = qa[1], c0 = ca[0], c1 = ca[1];
        acc[0] += f * q0.x - h * c0.x;  acc[1] += f * q0.y - h * c0.y;
        acc[2] += f * q0.z - h * c0.z;  acc[3] += f * q0.w - h * c0.w;
        acc[4] += f * q1.x - h * c1.x;  acc[5] += f * q1.y - h * c1.y;
        acc[6] += f * q1.z - h * c1.z;  acc[7] += f * q1.w - h * c1.w;
    }
    float4* cv = (float4*)(g_c + (size_t)gid * 8);
    cv[0] = make_float4(acc[0], acc[1], acc[2], acc[3]);
    cv[1] = make_float4(acc[4], acc[5], acc[6], acc[7]);
}

// ---------------------------------------------------------------------------
// Kernel 3: main attention — EXACT R3 structure (duplicated {w,w} weight
// pairs, lds64 wtp, gmem pe_w2 epilogue) + two LDS deletions:
//   (a) ik folded into s_ikd.w (1 LDS.128/k instead of 2 loads)
//   (b) logit weights read as float4 rows (18 LDS.128 instead of ~72 LDS.32)
// ---------------------------------------------------------------------------
// smem float layout:
//   0     s_we2  [64]                  we_w2 row-major [gp][gg]
//   64    s_web2 [8]
//   72    s_ikd  [8*16 float4] = 512   {dx,dy,dz,ik_bits}
//   584   s_w    [8*16*16] = 2048      duplicated {w,w} pairs, 16 f/edge
//   2632  s_H    [8 * 576]             8 rows x 72 floats per center
//   (s_out 64x9 overlays s_H after full-block sync)
#define SM_WE2   0
#define SM_WEB2  64
#define SM_IKD   72
#define SM_W     584
#define SM_H     2632
#define SM_TOT   (2632 + 8 * 576)

__global__ void __launch_bounds__(128, 5)
attn_kernel(const float* __restrict__ center_pos,
            const float* __restrict__ pos,
            const int* __restrict__ idx,
            const float* __restrict__ pe_w2,
            const float* __restrict__ pe_b,
            const float* __restrict__ pe_b2,
            const float* __restrict__ we_w2,
            const float* __restrict__ we_b2,
            float* __restrict__ out) {
    extern __shared__ float sm[];
    float*  s_we2  = sm + SM_WE2;
    float*  s_web2 = sm + SM_WEB2;
    float4* s_ikd  = (float4*)(sm + SM_IKD);
    float4* s_w4   = (float4*)(sm + SM_W);
    float*  s_H    = sm + SM_H;

    const int tid = threadIdx.x;
    if (tid < 64) s_we2[tid] = we_w2[tid];
    if (tid < 8)  s_web2[tid] = we_b2[tid];
    __syncthreads();

    const unsigned FULL = 0xffffffffu;
    const int ci = tid >> 4;           // center within block (0..7)
    const int t  = tid & 15;           // lane within center
    const int g  = t >> 1;             // my output group
    const int gidBase = blockIdx.x * 8;
    const int gid = gidBase + ci;
    const int b = gid >> 14;

    const uint32_t aBase = (uint32_t)__cvta_generic_to_shared(sm);
    const uint32_t aW    = aBase + SM_W * 4 + ci * 1024;   // this center's w-pairs

    // --- prologue: my edge (k = t) ---
    int myik;
    {
        int ik = idx[(size_t)gid * 16 + t];
        myik = b * PN + ik;
        const float* pp = pos + (size_t)myik * 3;
        float cx = center_pos[(size_t)gid * 3 + 0];
        float cy = center_pos[(size_t)gid * 3 + 1];
        float cz = center_pos[(size_t)gid * 3 + 2];
        s_ikd[ci * 16 + t] = make_float4(pp[0] - cx, pp[1] - cy, pp[2] - cz,
                                         __int_as_float(myik));
    }

    // --- logits + softmax for my edge (R3 math, vectorized weight reads) ---
    {
        const float4* cpv = (const float4*)(g_c + (size_t)gid * 8);
        float4 cA = cpv[0], cB = cpv[1];
        const float4* ap = (const float4*)(g_a + (size_t)myik * 8);
        float4 a0 = ap[0], a1 = ap[1];
        float h1[8];
        h1[0] = fmaxf(a0.x - cA.x, 0.f); h1[1] = fmaxf(a0.y - cA.y, 0.f);
        h1[2] = fmaxf(a0.z - cA.z, 0.f); h1[3] = fmaxf(a0.w - cA.w, 0.f);
        h1[4] = fmaxf(a1.x - cB.x, 0.f); h1[5] = fmaxf(a1.y - cB.y, 0.f);
        h1[6] = fmaxf(a1.z - cB.z, 0.f); h1[7] = fmaxf(a1.w - cB.w, 0.f);

        float4 b0 = *(const float4*)(s_web2);
        float4 b1 = *(const float4*)(s_web2 + 4);
        float lg[8] = {b0.x, b0.y, b0.z, b0.w, b1.x, b1.y, b1.z, b1.w};
        #pragma unroll
        for (int gp = 0; gp < 8; gp++) {
            float hv = h1[gp];
            float4 wa = *(const float4*)(s_we2 + gp * 8);
            float4 wb = *(const float4*)(s_we2 + gp * 8 + 4);
            lg[0] = fmaf(hv, wa.x, lg[0]); lg[1] = fmaf(hv, wa.y, lg[1]);
            lg[2] = fmaf(hv, wa.z, lg[2]); lg[3] = fmaf(hv, wa.w, lg[3]);
            lg[4] = fmaf(hv, wb.x, lg[4]); lg[5] = fmaf(hv, wb.y, lg[5]);
            lg[6] = fmaf(hv, wb.z, lg[6]); lg[7] = fmaf(hv, wb.w, lg[7]);
        }
        float mx[8];
        #pragma unroll
        for (int gg = 0; gg < 8; gg++) mx[gg] = lg[gg];
        #pragma unroll
        for (int s = 1; s < 16; s <<= 1)
            #pragma unroll
            for (int gg = 0; gg < 8; gg++)
                mx[gg] = fmaxf(mx[gg], __shfl_xor_sync(FULL, mx[gg], s, 16));
        float e[8], sum[8];
        #pragma unroll
        for (int gg = 0; gg < 8; gg++) { e[gg] = __expf(lg[gg] - mx[gg]); sum[gg] = e[gg]; }
        #pragma unroll
        for (int s = 1; s < 16; s <<= 1)
            #pragma unroll
            for (int gg = 0; gg < 8; gg++)
                sum[gg] += __shfl_xor_sync(FULL, sum[gg], s, 16);
        #pragma unroll
        for (int gg = 0; gg < 8; gg++)
            e[gg] *= __fdividef(1.f, sum[gg]);
        // duplicated {w,w} pairs: 16 floats per edge
        float4* wb4 = s_w4 + (ci * 16 + t) * 4;
        wb4[0] = make_float4(e[0], e[0], e[1], e[1]);
        wb4[1] = make_float4(e[2], e[2], e[3], e[3]);
        wb4[2] = make_float4(e[4], e[4], e[5], e[5]);
        wb4[3] = make_float4(e[6], e[6], e[7], e[7]);
    }
    __syncwarp();

    // --- per-thread pe_w1 slice (folded with pe_s) + bias ---
    float wxa[4], wxb[4], wxc[4], bb[4];
    #pragma unroll
    for (int jj = 0; jj < 4; jj++) {
        wxa[jj] = __ldg(g_pw1f + 0 * 64 + t * 4 + jj);
        wxb[jj] = __ldg(g_pw1f + 1 * 64 + t * 4 + jj);
        wxc[jj] = __ldg(g_pw1f + 2 * 64 + t * 4 + jj);
        bb[jj]  = __ldg(pe_b + t * 4 + jj);
    }

    // --- edge loop (R3 structure, single s_ikd load per k) ---
    ull Hc2[16];           // Hc2[gg*2+p] = {H[gg][j-pair p]}
    ull onv2[2] = {0ull, 0ull};
    #pragma unroll
    for (int i = 0; i < 16; i++) Hc2[i] = 0ull;

    #pragma unroll
    for (int k = 0; k < 16; k++) {
        float4 d = *(float4*)((char*)sm + (SM_IKD * 4 + ci * 256 + k * 16));
        int ikk = __float_as_int(d.w);
        ull wp0, wp1, wp2, wp3, wp4, wp5, wp6, wp7;
        lds128(wp0, wp1, aW + k * 64);
        lds128(wp2, wp3, aW + k * 64 + 16);
        lds128(wp4, wp5, aW + k * 64 + 32);
        lds128(wp6, wp7, aW + k * 64 + 48);
        ull wtp = lds64(aW + k * 64 + g * 8);
        ull v0, v1;
        ldg128(v0, v1, g_xv + (size_t)ikk * 64 + t * 4);

        float h0 = fmaxf(fmaf(d.x, wxa[0], fmaf(d.y, wxb[0], fmaf(d.z, wxc[0], bb[0]))), 0.f);
        float h1 = fmaxf(fmaf(d.x, wxa[1], fmaf(d.y, wxb[1], fmaf(d.z, wxc[1], bb[1]))), 0.f);
        float h2 = fmaxf(fmaf(d.x, wxa[2], fmaf(d.y, wxb[2], fmaf(d.z, wxc[2], bb[2]))), 0.f);
        float h3 = fmaxf(fmaf(d.x, wxa[3], fmaf(d.y, wxb[3], fmaf(d.z, wxc[3], bb[3]))), 0.f);
        ull h01 = pack2(h0, h1);
        ull h23 = pack2(h2, h3);

        ffma2(Hc2[0],  wp0, h01, Hc2[0]);  ffma2(Hc2[1],  wp0, h23, Hc2[1]);
        ffma2(Hc2[2],  wp1, h01, Hc2[2]);  ffma2(Hc2[3],  wp1, h23, Hc2[3]);
        ffma2(Hc2[4],  wp2, h01, Hc2[4]);  ffma2(Hc2[5],  wp2, h23, Hc2[5]);
        ffma2(Hc2[6],  wp3, h01, Hc2[6]);  ffma2(Hc2[7],  wp3, h23, Hc2[7]);
        ffma2(Hc2[8],  wp4, h01, Hc2[8]);  ffma2(Hc2[9],  wp4, h23, Hc2[9]);
        ffma2(Hc2[10], wp5, h01, Hc2[10]); ffma2(Hc2[11], wp5, h23, Hc2[11]);
        ffma2(Hc2[12], wp6, h01, Hc2[12]); ffma2(Hc2[13], wp6, h23, Hc2[13]);
        ffma2(Hc2[14], wp7, h01, Hc2[14]); ffma2(Hc2[15], wp7, h23, Hc2[15]);

        ffma2(onv2[0], wtp, v0, onv2[0]);
        ffma2(onv2[1], wtp, v1, onv2[1]);
    }

    // --- H transpose through smem (warp-local) ---
    {
        uint32_t aH = aBase + SM_H * 4 + ci * 2304 + t * 16;
        #pragma unroll
        for (int gg = 0; gg < 8; gg++)
            sts128(aH + gg * 288, Hc2[gg * 2], Hc2[gg * 2 + 1]);
    }
    __syncwarp();

    // --- final contraction: pr pairs = pe_b2 + H[g]·pe_w2[:,t*4..t*4+3] ---
    ull pr0 = pack2(__ldg(pe_b2 + t * 4 + 0), __ldg(pe_b2 + t * 4 + 1));
    ull pr1 = pack2(__ldg(pe_b2 + t * 4 + 2), __ldg(pe_b2 + t * 4 + 3));
    {
        const float* hrow = s_H + ci * 576 + g * 72;
        const float* pwb = pe_w2 + t * 4;
        #pragma unroll 4
        for (int j4 = 0; j4 < 16; j4++) {
            float4 hv = *(const float4*)(hrow + j4 * 4);
            ull p0, p1;
            ull hp;
            hp = pack2(hv.x, hv.x);
            ldg128(p0, p1, pwb + (j4 * 4 + 0) * 64);
            ffma2(pr0, hp, p0, pr0); ffma2(pr1, hp, p1, pr1);
            hp = pack2(hv.y, hv.y);
            ldg128(p0, p1, pwb + (j4 * 4 + 1) * 64);
            ffma2(pr0, hp, p0, pr0); ffma2(pr1, hp, p1, pr1);
            hp = pack2(hv.z, hv.z);
            ldg128(p0, p1, pwb + (j4 * 4 + 2) * 64);
            ffma2(pr0, hp, p0, pr0); ffma2(pr1, hp, p1, pr1);
            hp = pack2(hv.w, hv.w);
            ldg128(p0, p1, pwb + (j4 * 4 + 3) * 64);
            ffma2(pr0, hp, p0, pr0); ffma2(pr1, hp, p1, pr1);
        }
    }
    __syncthreads();   // all warps done with s_H — safe to overlay s_out

    // --- stage output [o][m_local] for coalesced [B,O,M] writes ---
    float* s_out = s_H;   // 64 x 9 overlay
    {
        float2 a0 = unpack2(onv2[0]), a1 = unpack2(onv2[1]);
        float2 q0 = unpack2(pr0),     q1 = unpack2(pr1);
        s_out[(t * 4 + 0) * 9 + ci] = a0.x + q0.x;
        s_out[(t * 4 + 1) * 9 + ci] = a0.y + q0.y;
        s_out[(t * 4 + 2) * 9 + ci] = a1.x + q1.x;
        s_out[(t * 4 + 3) * 9 + ci] = a1.y + q1.y;
    }
    __syncthreads();

    const int m0 = gidBase & (PM - 1);
    float* ob = out + (size_t)(gidBase >> 14) * PO * PM + m0;
    #pragma unroll
    for (int q = 0; q < 4; q++) {
        int lin = q * 128 + tid;
        int o = lin >> 3;
        int ml = lin & 7;
        ob[(size_t)o * PM + ml] = s_out[o * 9 + ml];
    }
}

// ---------------------------------------------------------------------------
extern "C" void kernel_launch(void* const* d_in, const int* in_sizes, int n_in,
                              void* d_out, int out_size) {
    (void)in_sizes; (void)n_in; (void)out_size;
    const float* center_pos = (const float*)d_in[0];
    const float* center_fea = (const float*)d_in[1];
    const float* pos        = (const float*)d_in[2];
    const float* fea        = (const float*)d_in[3];
    const int*   idx        = (const int*)d_in[4];
    const float* Wq  = (const float*)d_in[5];
    const float* bq  = (const float*)d_in[6];
    const float* Wk  = (const float*)d_in[7];
    const float* bk  = (const float*)d_in[8];
    const float* Wv  = (const float*)d_in[9];
    const float* bv  = (const float*)d_in[10];
    const float* cpe_w1 = (const float*)d_in[11];
    const float* cpe_s  = (const float*)d_in[12];
    const float* cpe_b  = (const float*)d_in[13];
    const float* cpe_w2 = (const float*)d_in[14];
    const float* cpe_b2 = (const float*)d_in[15];
    const float* pe_w1  = (const float*)d_in[16];
    const float* pe_s   = (const float*)d_in[17];
    const float* pe_b   = (const float*)d_in[18];
    const float* pe_w2  = (const float*)d_in[19];
    const float* pe_b2  = (const float*)d_in[20];
    const float* we_w1  = (const float*)d_in[21];
    const float* we_s   = (const float*)d_in[22];
    const float* we_b   = (const float*)d_in[23];
    const float* we_w2  = (const float*)d_in[24];
    const float* we_b2  = (const float*)d_in[25];
    float* out = (float*)d_out;

    fold_kernel<<<1, 512>>>(Wq, bq, Wk, bk, cpe_w1, cpe_s, cpe_w2, cpe_b2,
                            pe_w1, pe_s, we_w1, we_s, we_b);
    point_kernel<<<(PB * PN) / 256, 128>>>(fea, Wv, bv);
    center_kernel<<<(PB * PM) / 256, 256>>>(center_pos, center_fea, cpe_b);

    const int smem = SM_TOT * 4;   // ~28.3 KB
    cudaFuncSetAttribute(attn_kernel, cudaFuncAttributeMaxDynamicSharedMemorySize, smem);
    attn_kernel<<<(PB * PM) / 8, 128, smem>>>(center_pos, pos, idx,
                                              pe_w2, pe_b, pe_b2, we_w2, we_b2, out);
}